// round 17
// baseline (speedup 1.0000x reference)
#include <cuda_runtime.h>
#include <cuda_bf16.h>
#include <cstdint>
#include <cstddef>

// ---------------------------------------------------------------------------
// Scratch (__device__ globals; no cudaMalloc allowed)
// ---------------------------------------------------------------------------
__device__ float g_c[64];
__device__ __align__(16) __nv_bfloat16 g_Mhi[64 * 1024];
__device__ __align__(16) __nv_bfloat16 g_Mlo[64 * 1024];
__device__ __align__(16) float g_feat[8192 * 64];   // partial accumulator (2 MB, L2-resident)

// ---------------------------------------------------------------------------
// Kernel A (per 256-wide d-chunk): M[k,d] = V[k,d] + W[k,d,:]·x2 -> bf16 hi/lo
// grid 2048, 8 warps/block, one (k,d) pair per warp. Streams 64 MB of W.
// ---------------------------------------------------------------------------
__global__ __launch_bounds__(256) void wx2_chunk(const float* __restrict__ W,
                                                 const float* __restrict__ V,
                                                 const float* __restrict__ x2,
                                                 int ch) {
    __shared__ float sx2[1024];
    {
        const float4* src = reinterpret_cast<const float4*>(x2);
        float4* dst = reinterpret_cast<float4*>(sx2);
        dst[threadIdx.x] = src[threadIdx.x];
    }
    __syncthreads();

    int rem = blockIdx.x * 8 + (threadIdx.x >> 5);   // 0..16383
    int lane = threadIdx.x & 31;
    int k = rem >> 8;                                // 0..63
    int d = ch * 256 + (rem & 255);
    int pair = k * 1024 + d;

    const float4* w = reinterpret_cast<const float4*>(W + (size_t)pair * 1024);
    const float4* xx = reinterpret_cast<const float4*>(sx2);

    float s = 0.0f;
#pragma unroll
    for (int i = 0; i < 8; i++) {
        float4 wv = __ldcs(&w[lane + i * 32]);       // W touched exactly once
        float4 xv = xx[lane + i * 32];
        s += wv.x * xv.x + wv.y * xv.y + wv.z * xv.z + wv.w * xv.w;
    }
#pragma unroll
    for (int o = 16; o; o >>= 1) s += __shfl_xor_sync(0xFFFFFFFFu, s, o);

    if (lane == 0) {
        float m = s + V[(size_t)k * 2048 + d];
        __nv_bfloat16 hi = __float2bfloat16_rn(m);
        __nv_bfloat16 lo = __float2bfloat16_rn(m - __bfloat162float(hi));
        g_Mhi[pair] = hi;
        g_Mlo[pair] = lo;
    }
}

// ---------------------------------------------------------------------------
// Kernel A2: c[k] = b[k] + V2[k]·x2
// ---------------------------------------------------------------------------
__global__ void c_kernel(const float* __restrict__ V,
                         const float* __restrict__ x2,
                         const float* __restrict__ b) {
    int k = blockIdx.x;
    int lane = threadIdx.x;
    const float4* v = reinterpret_cast<const float4*>(V + (size_t)k * 2048 + 1024);
    const float4* xx = reinterpret_cast<const float4*>(x2);
    float s = 0.0f;
#pragma unroll
    for (int i = 0; i < 8; i++) {
        float4 a = v[lane + i * 32];
        float4 c = xx[lane + i * 32];
        s += a.x * c.x + a.y * c.y + a.z * c.z + a.w * c.w;
    }
#pragma unroll
    for (int o = 16; o; o >>= 1) s += __shfl_xor_sync(0xFFFFFFFFu, s, o);
    if (lane == 0) g_c[k] = s + b[k];
}

// ---------------------------------------------------------------------------
// Kernel B (x4 partials): partial GEMM over K=256 columns, accumulate into
// g_feat; last partial fuses feat + c -> relu -> ·U -> row-reduce -> out.
// 128 CTAs (BM=64), 256 thr (8 warps: 4x2, warp tile 16m x 32n).
// Each partial runs as soon as its wx2 chunk's event fires (pure event deps,
// no spin-waits -> ncu-safe).
// ---------------------------------------------------------------------------
#define LDA       136
#define A_HI      0
#define A_LO      17408
#define B_HI      34816
#define B_LO      52224
#define STAGE_BYTES 69632
#define RED_OFF   (2 * STAGE_BYTES)      // 139264
#define SMEM_TOTAL (RED_OFF + 512)       // 139776

__device__ __forceinline__ uint32_t smem_u32(const void* p) {
    return (uint32_t)__cvta_generic_to_shared(p);
}

#define CP_ASYNC16(dst_u32, src_ptr) \
    asm volatile("cp.async.cg.shared.global [%0], [%1], 16;" :: "r"(dst_u32), "l"(src_ptr))
#define CP_COMMIT() asm volatile("cp.async.commit_group;" ::: "memory")
#define CP_WAIT0()  asm volatile("cp.async.wait_group 0;" ::: "memory")

__device__ __forceinline__ uint32_t pack_bf16x2(__nv_bfloat16 a, __nv_bfloat16 b) {
    __nv_bfloat162 t; t.x = a; t.y = b;
    return *reinterpret_cast<uint32_t*>(&t);
}

__device__ __forceinline__ void split_pair(float f0, float f1, uint32_t& h, uint32_t& l) {
    __nv_bfloat16 h0 = __float2bfloat16_rn(f0);
    __nv_bfloat16 h1 = __float2bfloat16_rn(f1);
    h = pack_bf16x2(h0, h1);
    l = pack_bf16x2(__float2bfloat16_rn(f0 - __bfloat162float(h0)),
                    __float2bfloat16_rn(f1 - __bfloat162float(h1)));
}

__device__ __forceinline__ void mma16816(float d[4], const uint32_t a[4],
                                         uint32_t b0, uint32_t b1) {
    asm volatile(
        "mma.sync.aligned.m16n8k16.row.col.f32.bf16.bf16.f32 "
        "{%0,%1,%2,%3}, {%4,%5,%6,%7}, {%8,%9}, {%0,%1,%2,%3};"
        : "+f"(d[0]), "+f"(d[1]), "+f"(d[2]), "+f"(d[3])
        : "r"(a[0]), "r"(a[1]), "r"(a[2]), "r"(a[3]), "r"(b0), "r"(b1));
}

// A sub-chunk (64 rows x 128 cols fp32) at absolute column base cb
__device__ __forceinline__ void ldg_a(const float* __restrict__ x1, int row0, int cb,
                                      int tid, float4 pa[8]) {
#pragma unroll
    for (int t = 0; t < 8; t++) {
        int g = tid + t * 256;
        int r = g >> 5;
        int c4 = (g & 31) * 4;
        pa[t] = *reinterpret_cast<const float4*>(x1 + (size_t)(row0 + r) * 1024 + cb + c4);
    }
}

__device__ __forceinline__ void sts_a(char* stage, int tid, const float4 pa[8]) {
#pragma unroll
    for (int t = 0; t < 8; t++) {
        int g = tid + t * 256;
        int r = g >> 5;
        int c4 = (g & 31) * 4;
        uint32_t h0, l0, h1, l1;
        split_pair(pa[t].x, pa[t].y, h0, l0);
        split_pair(pa[t].z, pa[t].w, h1, l1);
        int off = (r * LDA + c4) * 2;
        *reinterpret_cast<uint2*>(stage + A_HI + off) = make_uint2(h0, h1);
        *reinterpret_cast<uint2*>(stage + A_LO + off) = make_uint2(l0, l1);
    }
}

// B sub-chunk (64 n-rows x 128 cols bf16 hi/lo) at absolute column base cb
__device__ __forceinline__ void cpasync_b(char* stage, int cb, int tid) {
    uint32_t sh = smem_u32(stage + B_HI);
    uint32_t sl = smem_u32(stage + B_LO);
#pragma unroll
    for (int t = 0; t < 4; t++) {
        int g = tid + t * 256;
        int n = g >> 4;
        int u = g & 15;
        uint32_t doff = (uint32_t)(n * (LDA * 2) + u * 16);
        CP_ASYNC16(sh + doff, g_Mhi + (size_t)n * 1024 + cb + u * 8);
        CP_ASYNC16(sl + doff, g_Mlo + (size_t)n * 1024 + cb + u * 8);
    }
}

// Warp tile 16m x 32n over one 128-wide sub-chunk (R5's proven scalar path)
__device__ __forceinline__ void compute_chunk(const char* stage, int m0, int nb,
                                              int lane, float d[4][4]) {
    const __nv_bfloat16* Ah = reinterpret_cast<const __nv_bfloat16*>(stage + A_HI);
    const __nv_bfloat16* Al = reinterpret_cast<const __nv_bfloat16*>(stage + A_LO);
    const __nv_bfloat16* Bh = reinterpret_cast<const __nv_bfloat16*>(stage + B_HI);
    const __nv_bfloat16* Bl = reinterpret_cast<const __nv_bfloat16*>(stage + B_LO);
    int g = lane >> 2, tg2 = (lane & 3) * 2;
#pragma unroll
    for (int ks = 0; ks < 8; ks++) {
        int k0 = ks * 16;
        int abase = (m0 + g) * LDA + k0 + tg2;
        uint32_t ah[4], al[4];
        ah[0] = *reinterpret_cast<const uint32_t*>(Ah + abase);
        ah[1] = *reinterpret_cast<const uint32_t*>(Ah + abase + 8 * LDA);
        ah[2] = *reinterpret_cast<const uint32_t*>(Ah + abase + 8);
        ah[3] = *reinterpret_cast<const uint32_t*>(Ah + abase + 8 * LDA + 8);
        al[0] = *reinterpret_cast<const uint32_t*>(Al + abase);
        al[1] = *reinterpret_cast<const uint32_t*>(Al + abase + 8 * LDA);
        al[2] = *reinterpret_cast<const uint32_t*>(Al + abase + 8);
        al[3] = *reinterpret_cast<const uint32_t*>(Al + abase + 8 * LDA + 8);
#pragma unroll
        for (int j = 0; j < 4; j++) {
            int bbase = (nb + j * 8 + g) * LDA + k0 + tg2;
            uint32_t bh0 = *reinterpret_cast<const uint32_t*>(Bh + bbase);
            uint32_t bh1 = *reinterpret_cast<const uint32_t*>(Bh + bbase + 8);
            uint32_t bl0 = *reinterpret_cast<const uint32_t*>(Bl + bbase);
            uint32_t bl1 = *reinterpret_cast<const uint32_t*>(Bl + bbase + 8);
            mma16816(d[j], ah, bh0, bh1);
            mma16816(d[j], ah, bl0, bl1);
            mma16816(d[j], al, bh0, bh1);
        }
    }
}

__global__ __launch_bounds__(256, 1) void gemm_partial(const float* __restrict__ x1,
                                                       const float* __restrict__ U,
                                                       float* __restrict__ out,
                                                       int ch) {
    extern __shared__ char smem[];
    int tid = threadIdx.x, lane = tid & 31, wid = tid >> 5;
    int wr = wid & 3, wc = wid >> 2;
    int m0 = wr * 16, nb = wc * 32;
    int row0 = blockIdx.x * 64;
    float* red = reinterpret_cast<float*>(smem + RED_OFF);
    int cb = ch * 256;

    float d[4][4] = {};
    float4 pa[8];

    // Stage both 128-wide sub-chunks: B via cp.async, A via LDG->split->STS
    cpasync_b(smem, cb, tid);
    cpasync_b(smem + STAGE_BYTES, cb + 128, tid);
    CP_COMMIT();
    ldg_a(x1, row0, cb, tid, pa);
    sts_a(smem, tid, pa);
    ldg_a(x1, row0, cb + 128, tid, pa);
    sts_a(smem + STAGE_BYTES, tid, pa);
    CP_WAIT0();
    __syncthreads();

    compute_chunk(smem, m0, nb, lane, d);
    compute_chunk(smem + STAGE_BYTES, m0, nb, lane, d);

    int g = lane >> 2, tg2 = (lane & 3) * 2;
    int rowA = row0 + m0 + g, rowB = row0 + m0 + 8 + g;

    if (ch < 3) {
        // accumulate partial into g_feat (each element owned by one thread)
#pragma unroll
        for (int j = 0; j < 4; j++) {
            int col = nb + j * 8 + tg2;
            float2* fa = reinterpret_cast<float2*>(g_feat + (size_t)rowA * 64 + col);
            float2* fb = reinterpret_cast<float2*>(g_feat + (size_t)rowB * 64 + col);
            if (ch == 0) {
                *fa = make_float2(d[j][0], d[j][1]);
                *fb = make_float2(d[j][2], d[j][3]);
            } else {
                float2 va = *fa, vb = *fb;
                *fa = make_float2(va.x + d[j][0], va.y + d[j][1]);
                *fb = make_float2(vb.x + d[j][2], vb.y + d[j][3]);
            }
        }
    } else {
        // final: feat + d + c -> relu -> *U -> row-reduce -> out
        float accA = 0.0f, accB = 0.0f;
#pragma unroll
        for (int j = 0; j < 4; j++) {
            int col = nb + j * 8 + tg2;
            float c0 = g_c[col], c1 = g_c[col + 1];
            float u0 = U[col], u1 = U[col + 1];
            float2 va = *reinterpret_cast<const float2*>(g_feat + (size_t)rowA * 64 + col);
            float2 vb = *reinterpret_cast<const float2*>(g_feat + (size_t)rowB * 64 + col);
            accA += fmaxf(d[j][0] + va.x + c0, 0.0f) * u0 + fmaxf(d[j][1] + va.y + c1, 0.0f) * u1;
            accB += fmaxf(d[j][2] + vb.x + c0, 0.0f) * u0 + fmaxf(d[j][3] + vb.y + c1, 0.0f) * u1;
        }
        accA += __shfl_xor_sync(0xFFFFFFFFu, accA, 1);
        accA += __shfl_xor_sync(0xFFFFFFFFu, accA, 2);
        accB += __shfl_xor_sync(0xFFFFFFFFu, accB, 1);
        accB += __shfl_xor_sync(0xFFFFFFFFu, accB, 2);
        if ((lane & 3) == 0) {
            red[wc * 64 + m0 + g] = accA;
            red[wc * 64 + m0 + 8 + g] = accB;
        }
        __syncthreads();
        if (tid < 64) out[row0 + tid] = red[tid] + red[64 + tid];
    }
}

// ---------------------------------------------------------------------------
// Event-chained pipeline across two non-blocking streams. NO device spin-
// waits: dependencies are stream events only -> safe under ncu serialization
// and under graph capture; overlapped in the timed graph.
// ---------------------------------------------------------------------------
extern "C" void kernel_launch(void* const* d_in, const int* in_sizes, int n_in,
                              void* d_out, int out_size) {
    const float* x1 = (const float*)d_in[0];  // (8192, 1024)
    const float* x2 = (const float*)d_in[1];  // (1, 1024)
    const float* V  = (const float*)d_in[2];  // (64, 2048)
    const float* W  = (const float*)d_in[3];  // (64, 1024, 1024)
    const float* b  = (const float*)d_in[4];  // (64,)
    const float* U  = (const float*)d_in[5];  // (64, 1)
    float* out = (float*)d_out;               // (8192, 1)

    static cudaStream_t s1 = nullptr, s2 = nullptr;
    static cudaEvent_t ev_fork = nullptr, ev_ch[4], ev_j1 = nullptr, ev_j2 = nullptr;
    if (s1 == nullptr) {   // one-time creation (first call runs outside capture)
        cudaStreamCreateWithFlags(&s1, cudaStreamNonBlocking);
        cudaStreamCreateWithFlags(&s2, cudaStreamNonBlocking);
        cudaEventCreateWithFlags(&ev_fork, cudaEventDisableTiming);
        for (int i = 0; i < 4; i++) cudaEventCreateWithFlags(&ev_ch[i], cudaEventDisableTiming);
        cudaEventCreateWithFlags(&ev_j1, cudaEventDisableTiming);
        cudaEventCreateWithFlags(&ev_j2, cudaEventDisableTiming);
        cudaFuncSetAttribute(gemm_partial, cudaFuncAttributeMaxDynamicSharedMemorySize, SMEM_TOTAL);
    }

    cudaEventRecord(ev_fork, 0);
    cudaStreamWaitEvent(s1, ev_fork, 0);
    cudaStreamWaitEvent(s2, ev_fork, 0);

    // s2: stream W chunk by chunk (HBM-bound), signaling each chunk
    for (int ch = 0; ch < 4; ch++) {
        wx2_chunk<<<2048, 256, 0, s2>>>(W, V, x2, ch);
        cudaEventRecord(ev_ch[ch], s2);
    }

    // s1: c first, then one partial GEMM per chunk, gated only by events
    c_kernel<<<64, 32, 0, s1>>>(V, x2, b);
    for (int ch = 0; ch < 4; ch++) {
        cudaStreamWaitEvent(s1, ev_ch[ch], 0);
        gemm_partial<<<128, 256, SMEM_TOTAL, s1>>>(x1, U, out, ch);
    }

    cudaEventRecord(ev_j1, s1);
    cudaEventRecord(ev_j2, s2);
    cudaStreamWaitEvent(0, ev_j1, 0);
    cudaStreamWaitEvent(0, ev_j2, 0);
}